// round 9
// baseline (speedup 1.0000x reference)
#include <cuda_runtime.h>
#include <cuda_bf16.h>
#include <mma.h>
#include <math.h>

using namespace nvcuda;

// Problem constants
#define NGRAPH 256
#define NPG    62
#define NPAD   64
#define LLEN   800
#define NTHR   256

typedef unsigned int u32;

// ---- shared memory layout (float offsets) ----
// BUF0: layer io, row stride = FIN (max 160)          [0, 10240)
// BUF1 region (14336 floats): time-multiplexed:
//   - during L0/L1 GEMM: Ah/Al bf16 (floats 0..10239) + Bh/Bl chunk (10240..14335)
//   - after GEMM: bufHw fp32 (stride D) at float 0
//   - after L1: W2 (2048 fl) at +8192, W3 (512 fl) at +10240... (dead A region)
#define OFF_BUF0 0
#define OFF_BUF1 10240
#define SZ_BUF1  14336
#define OFF_W2   (OFF_BUF1 + 8192)
#define OFF_W3   (OFF_W2 + 2048)
#define OFF_ALS  (OFF_BUF1 + SZ_BUF1)     // stride-5 logits
#define OFF_ALD  (OFF_ALS + NPAD * 5)
#define OFF_SMAX (OFF_ALD + NPAD * 5)
#define OFF_GM   (OFF_SMAX + 8)
#define OFF_Z1   (OFF_GM + 16)
#define OFF_Z2   (OFF_Z1 + 16)
#define SMEM_FLOATS (OFF_Z2 + 8)
#define SMEM_BYTES  (SMEM_FLOATS * 4)

__device__ __forceinline__ float elu_f(float v) {
    return v > 0.0f ? v : (__expf(v) - 1.0f);
}

// ---- cp.async helpers (W2/W3 staging) ----
__device__ __forceinline__ void cp16(u32 saddr, const void* gptr) {
    asm volatile("cp.async.ca.shared.global [%0], [%1], 16;" :: "r"(saddr), "l"(gptr));
}
__device__ __forceinline__ void cp_commit() { asm volatile("cp.async.commit_group;"); }
__device__ __forceinline__ void cp_wait_all() { asm volatile("cp.async.wait_group 0;"); }
__device__ __forceinline__ void prefetch_w(float* sdst, const float* gsrc,
                                           int nfloats, int tid) {
    u32 sa = (u32)__cvta_generic_to_shared(sdst);
    for (int i = tid * 4; i < nfloats; i += NTHR * 4) cp16(sa + i * 4, gsrc + i);
    cp_commit();
}

// fp32 -> bf16 hi/lo split
__device__ __forceinline__ void split_bf16(float v, __nv_bfloat16* hp, __nv_bfloat16* lp) {
    __nv_bfloat16 hi = __float2bfloat16(v);
    *hp = hi;
    *lp = __float2bfloat16(v - __bfloat162float(hi));
}

// ---- WMMA bf16 2-split GEMM: bufHw[64, D] = bufIO[64, FIN] @ Wg[FIN, D] ----
// bufIO stride FIN (rows 62..63 zero). Result fp32, stride D, at OFF_BUF1.
template<int FIN, int D, int KC>
__device__ void wmma_gemm(float* __restrict__ smem, const float* __restrict__ Wg,
                          int tid) {
    constexpr int NCH = FIN / KC;
    static_assert(FIN % KC == 0, "chunking");
    constexpr int NT = D / 16;               // n-tiles (8 or 4)
    constexpr int TPW = 4 * NT / 8;          // tiles per warp (4 or 2)
    float* bufIO = smem + OFF_BUF0;
    float* bufHw = smem + OFF_BUF1;
    __nv_bfloat16* Ah = (__nv_bfloat16*)(smem + OFF_BUF1);
    __nv_bfloat16* Al = Ah + 64 * FIN;
    __nv_bfloat16* Bh = (__nv_bfloat16*)(smem + OFF_BUF1 + 10240);
    __nv_bfloat16* Bl = Bh + KC * D;

    // A convert: bufIO fp32 -> Ah/Al bf16 (same i = row*FIN + k indexing)
    for (int i = tid; i < 64 * FIN; i += NTHR)
        split_bf16(bufIO[i], Ah + i, Al + i);

    wmma::fragment<wmma::accumulator, 16, 16, 16, float> acc[TPW];
    #pragma unroll
    for (int j = 0; j < TPW; j++) wmma::fill_fragment(acc[j], 0.0f);

    const int wid = tid >> 5;
    const int mt = wid & 3;                  // m-tile (16 rows)
    const int nb = (wid >> 2) * TPW;         // first n-tile

    for (int ch = 0; ch < NCH; ch++) {
        // B chunk convert: W rows [ch*KC, ch*KC+KC), n fast -> coalesced LDG
        const float* wsrc = Wg + ch * KC * D;
        for (int i = tid; i < KC * D; i += NTHR)
            split_bf16(wsrc[i], Bh + i, Bl + i);
        __syncthreads();                     // converts visible; prev frag loads done
        #pragma unroll
        for (int ks = 0; ks < KC / 16; ks++) {
            wmma::fragment<wmma::matrix_a, 16, 16, 16, __nv_bfloat16, wmma::row_major> fah, fal;
            wmma::load_matrix_sync(fah, Ah + mt * 16 * FIN + ch * KC + ks * 16, FIN);
            wmma::load_matrix_sync(fal, Al + mt * 16 * FIN + ch * KC + ks * 16, FIN);
            #pragma unroll
            for (int j = 0; j < TPW; j++) {
                wmma::fragment<wmma::matrix_b, 16, 16, 16, __nv_bfloat16, wmma::row_major> fbh, fbl;
                wmma::load_matrix_sync(fbh, Bh + ks * 16 * D + (nb + j) * 16, D);
                wmma::load_matrix_sync(fbl, Bl + ks * 16 * D + (nb + j) * 16, D);
                wmma::mma_sync(acc[j], fah, fbh, acc[j]);
                wmma::mma_sync(acc[j], fah, fbl, acc[j]);
                wmma::mma_sync(acc[j], fal, fbh, acc[j]);
            }
        }
        __syncthreads();                     // all frag loads done before next convert
    }
    // store phase: operands dead, bufHw aliases Ah region
    #pragma unroll
    for (int j = 0; j < TPW; j++)
        wmma::store_matrix_sync(bufHw + mt * 16 * D + (nb + j) * 16, acc[j], D,
                                wmma::mem_row_major);
    __syncthreads();
}

// ---- scalar GEMM for small layers (W resident fp32 in smem) ----
template<int FIN, int F>
__device__ void scalar_gemm(float* __restrict__ smem, const float* __restrict__ Wsm,
                            int tid) {
    constexpr int D = 4 * F;
    constexpr int RT = D / 16, NT_J = D / 4;
    float* bufIO = smem + OFF_BUF0;
    float* bufHw = smem + OFF_BUF1;
    const int jt = tid % NT_J, nt = tid / NT_J;
    const int j0 = jt * 4, n0 = nt * RT;
    float acc[RT][4];
    #pragma unroll
    for (int r = 0; r < RT; r++) { acc[r][0] = acc[r][1] = acc[r][2] = acc[r][3] = 0.0f; }
    const float* hp = bufIO + n0 * FIN;
    #pragma unroll 4
    for (int k = 0; k < FIN; k += 4) {
        float4 a[RT];
        #pragma unroll
        for (int r = 0; r < RT; r++) a[r] = *(const float4*)(hp + r * FIN + k);
        #pragma unroll
        for (int kk = 0; kk < 4; kk++) {
            float4 w = *(const float4*)(Wsm + (k + kk) * D + j0);
            #pragma unroll
            for (int r = 0; r < RT; r++) {
                float av = kk == 0 ? a[r].x : kk == 1 ? a[r].y : kk == 2 ? a[r].z : a[r].w;
                acc[r][0] += av * w.x; acc[r][1] += av * w.y;
                acc[r][2] += av * w.z; acc[r][3] += av * w.w;
            }
        }
    }
    #pragma unroll
    for (int r = 0; r < RT; r++)
        *(float4*)(bufHw + (n0 + r) * D + j0) =
            make_float4(acc[r][0], acc[r][1], acc[r][2], acc[r][3]);
    __syncthreads();
}

// ---- attention phase: logits + per-target softmax aggregation (R7-proven) ----
template<int F>
__device__ void attention(float* __restrict__ smem,
                          const float* __restrict__ a_s, const float* __restrict__ a_d,
                          const float* __restrict__ bias, bool apply_elu, int tid) {
    constexpr int D = 4 * F, F4 = F / 4;
    float* bufIO = smem + OFF_BUF0;
    const float* hw = smem + OFF_BUF1;
    float* als = smem + OFF_ALS;
    float* ald = smem + OFF_ALD;
    float* smax = smem + OFF_SMAX;

    if (tid < NPG * 4) {
        int n = tid % NPG, h = tid / NPG;
        const float* hr = hw + n * D + h * F;
        float s1 = 0.0f, s2 = 0.0f;
        #pragma unroll
        for (int q = 0; q < F4; q++) {
            float4 v = *(const float4*)(hr + q * 4);
            float4 cs = *(const float4*)(a_s + h * F + q * 4);
            float4 cd = *(const float4*)(a_d + h * F + q * 4);
            s1 += v.x * cs.x + v.y * cs.y + v.z * cs.z + v.w * cs.w;
            s2 += v.x * cd.x + v.y * cd.y + v.z * cd.z + v.w * cd.w;
        }
        als[n * 5 + h] = s1;
        ald[n * 5 + h] = s2;
    }
    __syncthreads();
    if (tid < 128) {
        int h = tid >> 5, ln = tid & 31;
        float m2 = als[ln * 5 + h];
        if (ln + 32 < NPG) m2 = fmaxf(m2, als[(ln + 32) * 5 + h]);
        #pragma unroll
        for (int off = 16; off > 0; off >>= 1)
            m2 = fmaxf(m2, __shfl_xor_sync(0xffffffff, m2, off));
        if (ln == 0) smax[h] = m2;
    }
    __syncthreads();

    // segment_max == lrelu(max_s al_s + al_d) by monotonicity of leaky_relu.
    if (tid < NPG * 4) {
        int d = tid % NPG, h = tid / NPG;    // lanes share h -> hw reads broadcast
        float adv = ald[d * 5 + h];
        float sm = smax[h] + adv;
        float m = fmaxf(sm, 0.2f * sm);
        float den = 0.0f;
        float4 aacc[F4];
        #pragma unroll
        for (int q = 0; q < F4; q++) aacc[q] = make_float4(0.f, 0.f, 0.f, 0.f);
        const float* hwp = hw + h * F;
        #pragma unroll 2
        for (int s = 0; s < NPG; s++) {
            float xv = als[s * 5 + h] + adv;
            float e = fmaxf(xv, 0.2f * xv);
            float w = __expf(e - m);
            den += w;
            const float* hr = hwp + s * D;
            #pragma unroll
            for (int q = 0; q < F4; q++) {
                float4 v = *(const float4*)(hr + q * 4);
                aacc[q].x += w * v.x; aacc[q].y += w * v.y;
                aacc[q].z += w * v.z; aacc[q].w += w * v.w;
            }
        }
        float inv = 1.0f / den;
        float* orow = bufIO + d * D + h * F;
        const float* bp = bias + h * F;
        #pragma unroll
        for (int q = 0; q < F4; q++) {
            float4 bv = *(const float4*)(bp + q * 4);
            float4 o;
            o.x = aacc[q].x * inv + bv.x; o.y = aacc[q].y * inv + bv.y;
            o.z = aacc[q].z * inv + bv.z; o.w = aacc[q].w * inv + bv.w;
            if (apply_elu) { o.x = elu_f(o.x); o.y = elu_f(o.y); o.z = elu_f(o.z); o.w = elu_f(o.w); }
            *(float4*)(orow + q * 4) = o;
        }
    }
    // zero padded rows 62..63 of the (re-striped) output
    for (int i = tid; i < 2 * D; i += NTHR) bufIO[NPG * D + i] = 0.0f;
    __syncthreads();
}

__global__ void __launch_bounds__(NTHR, 2)
eeg_gat_kernel(const float* __restrict__ x,
               const float* __restrict__ mcf_w, const float* __restrict__ mcf_b,
               const float* __restrict__ W0, const float* __restrict__ as0,
               const float* __restrict__ ad0, const float* __restrict__ b0,
               const float* __restrict__ W1, const float* __restrict__ as1,
               const float* __restrict__ ad1, const float* __restrict__ b1,
               const float* __restrict__ W2, const float* __restrict__ as2,
               const float* __restrict__ ad2, const float* __restrict__ b2,
               const float* __restrict__ W3, const float* __restrict__ as3,
               const float* __restrict__ ad3, const float* __restrict__ b3,
               const float* __restrict__ Wm1, const float* __restrict__ bm1,
               const float* __restrict__ Wm2, const float* __restrict__ bm2,
               const float* __restrict__ Wm3, const float* __restrict__ bm3,
               float* __restrict__ out) {
    extern __shared__ float smem[];
    const int tid = threadIdx.x;
    const int g = blockIdx.x;

    float* buf0 = smem + OFF_BUF0;

    // ---- EEG_MCf: stride-5 conv + ELU -> h0 [62, 160] (stride 160) ----
    float cw0 = mcf_w[0], cw1 = mcf_w[1], cw2 = mcf_w[2], cw3 = mcf_w[3], cw4 = mcf_w[4];
    float cb = mcf_b[0];
    for (int slot = tid; slot < NPG * 40; slot += NTHR) {
        int n = slot / 40, p = slot % 40;
        const float4* xp = (const float4*)(x + ((size_t)g * NPG + n) * LLEN + p * 20);
        float4 v0 = xp[0], v1 = xp[1], v2 = xp[2], v3 = xp[3], v4 = xp[4];
        float4 o;
        o.x = elu_f(v0.x * cw0 + v0.y * cw1 + v0.z * cw2 + v0.w * cw3 + v1.x * cw4 + cb);
        o.y = elu_f(v1.y * cw0 + v1.z * cw1 + v1.w * cw2 + v2.x * cw3 + v2.y * cw4 + cb);
        o.z = elu_f(v2.z * cw0 + v2.w * cw1 + v3.x * cw2 + v3.y * cw3 + v3.z * cw4 + cb);
        o.w = elu_f(v3.w * cw0 + v4.x * cw1 + v4.y * cw2 + v4.z * cw3 + v4.w * cw4 + cb);
        *(float4*)(buf0 + n * 160 + p * 4) = o;
    }
    for (int i = tid; i < 2 * 160; i += NTHR) buf0[NPG * 160 + i] = 0.0f;
    __syncthreads();

    // ---- L0/L1: WMMA bf16 2-split GEMM + scalar attention ----
    wmma_gemm<160, 128, 32>(smem, W0, tid);
    attention<32>(smem, as0, ad0, b0, true, tid);

    wmma_gemm<128, 64, 32>(smem, W1, tid);
    // stage W2/W3 fp32 into dead A region; overlaps L1 attention
    prefetch_w(smem + OFF_W2, W2, 64 * 32, tid);
    prefetch_w(smem + OFF_W3, W3, 32 * 16, tid);
    attention<16>(smem, as1, ad1, b1, true, tid);

    // ---- L2/L3: scalar GEMM + attention ----
    cp_wait_all();
    __syncthreads();
    scalar_gemm<64, 8>(smem, smem + OFF_W2, tid);
    attention<8>(smem, as2, ad2, b2, true, tid);
    scalar_gemm<32, 4>(smem, smem + OFF_W3, tid);
    attention<4>(smem, as3, ad3, b3, false, tid);
    // buf0 holds h3 [62, 16] stride 16 (rows 62..63 zero)

    // ---- embeddings output: tuple = (z, embeddings); z occupies [0, 1024) ----
    float* emb_out = out + NGRAPH * 4 + (size_t)g * (NPG * 16);
    for (int i = tid; i < NPG * 16; i += NTHR) emb_out[i] = buf0[i];

    // ---- global mean pool + MLP head ----
    float* gm = smem + OFF_GM;
    float* z1 = smem + OFF_Z1;
    float* z2 = smem + OFF_Z2;
    if (tid < 16) {
        float s = 0.0f;
        for (int d = 0; d < NPG; d++) s += buf0[d * 16 + tid];
        gm[tid] = s / 62.0f;
    }
    __syncthreads();
    if (tid < 16) {
        float s = bm1[tid];
        #pragma unroll
        for (int i = 0; i < 16; i++) s += gm[i] * Wm1[i * 16 + tid];
        z1[tid] = fmaxf(s, 0.0f);
    }
    __syncthreads();
    if (tid < 8) {
        float s = bm2[tid];
        #pragma unroll
        for (int i = 0; i < 16; i++) s += z1[i] * Wm2[i * 8 + tid];
        z2[tid] = fmaxf(s, 0.0f);
    }
    __syncthreads();
    if (tid < 4) {
        float s = bm3[tid];
        #pragma unroll
        for (int i = 0; i < 8; i++) s += z2[i] * Wm3[i * 4 + tid];
        out[g * 4 + tid] = s;
    }
}

extern "C" void kernel_launch(void* const* d_in, const int* in_sizes, int n_in,
                              void* d_out, int out_size) {
    const float* x     = (const float*)d_in[0];
    // d_in[1] = edge_index, d_in[2] = batch: fixed block-diagonal complete graph,
    // exploited analytically.
    const float* mcf_w = (const float*)d_in[3];
    const float* mcf_b = (const float*)d_in[4];
    const float* W0  = (const float*)d_in[5];
    const float* as0 = (const float*)d_in[6];
    const float* ad0 = (const float*)d_in[7];
    const float* b0  = (const float*)d_in[8];
    const float* W1  = (const float*)d_in[9];
    const float* as1 = (const float*)d_in[10];
    const float* ad1 = (const float*)d_in[11];
    const float* b1  = (const float*)d_in[12];
    const float* W2  = (const float*)d_in[13];
    const float* as2 = (const float*)d_in[14];
    const float* ad2 = (const float*)d_in[15];
    const float* b2  = (const float*)d_in[16];
    const float* W3  = (const float*)d_in[17];
    const float* as3 = (const float*)d_in[18];
    const float* ad3 = (const float*)d_in[19];
    const float* b3  = (const float*)d_in[20];
    const float* Wm1 = (const float*)d_in[21];
    const float* bm1 = (const float*)d_in[22];
    const float* Wm2 = (const float*)d_in[23];
    const float* bm2 = (const float*)d_in[24];
    const float* Wm3 = (const float*)d_in[25];
    const float* bm3 = (const float*)d_in[26];
    float* out = (float*)d_out;

    cudaFuncSetAttribute(eeg_gat_kernel,
                         cudaFuncAttributeMaxDynamicSharedMemorySize, SMEM_BYTES);
    eeg_gat_kernel<<<NGRAPH, NTHR, SMEM_BYTES>>>(
        x, mcf_w, mcf_b,
        W0, as0, ad0, b0, W1, as1, ad1, b1,
        W2, as2, ad2, b2, W3, as3, ad3, b3,
        Wm1, bm1, Wm2, bm2, Wm3, bm3, out);
}

// round 10
// speedup vs baseline: 1.7080x; 1.7080x over previous
#include <cuda_runtime.h>
#include <cuda_bf16.h>
#include <math.h>

// Problem constants
#define NGRAPH 256
#define NPG    62
#define NPAD   64
#define LLEN   800
#define NTHR   256

typedef unsigned int u32;

// ---- shared memory layout ----
// bufIO: layer io, row stride = FIN+4 (max 164)       floats [0, 10496)
// CH region (49152 B): per-chunk MMA operands (Ah/Al/Bh/Bl bf16), then
//   aliased by bufHw fp32 (stride D+4) after the GEMM, and W2/W3 stage.
#define OFF_BUF0 0
#define OFF_CH   10496                     // float offset; byte 41984 (128B-aligned)
#define CHB_AH   0                         // byte offsets within CH
#define CHB_AL   8192
#define CHB_BH   16384
#define CHB_BL   32768
#define CHB_W2   34816
#define CHB_W3   43008
#define OFF_ALS  (OFF_CH + 12288)          // after 49152B CH region
#define OFF_ALD  (OFF_ALS + NPAD * 5)
#define OFF_SMAX (OFF_ALD + NPAD * 5)
#define OFF_GM   (OFF_SMAX + 8)
#define OFF_Z1   (OFF_GM + 16)
#define OFF_Z2   (OFF_Z1 + 16)
#define SMEM_FLOATS (OFF_Z2 + 8)
#define SMEM_BYTES  (SMEM_FLOATS * 4)

__device__ __forceinline__ float elu_f(float v) {
    return v > 0.0f ? v : (__expf(v) - 1.0f);
}

// ---- cp.async helpers ----
__device__ __forceinline__ void cp16(u32 saddr, const void* gptr) {
    asm volatile("cp.async.ca.shared.global [%0], [%1], 16;" :: "r"(saddr), "l"(gptr));
}
__device__ __forceinline__ void cp_commit() { asm volatile("cp.async.commit_group;"); }
__device__ __forceinline__ void cp_wait_all() { asm volatile("cp.async.wait_group 0;"); }
__device__ __forceinline__ void prefetch_w(float* sdst, const float* gsrc,
                                           int nfloats, int tid) {
    u32 sa = (u32)__cvta_generic_to_shared(sdst);
    for (int i = tid * 4; i < nfloats; i += NTHR * 4) cp16(sa + i * 4, gsrc + i);
    cp_commit();
}

// pack two fp32 into bf16x2 hi and lo (residual) words
__device__ __forceinline__ void split2(float v0, float v1, u32& hi, u32& lo) {
    __nv_bfloat16 h0 = __float2bfloat16(v0), h1 = __float2bfloat16(v1);
    __nv_bfloat16 l0 = __float2bfloat16(v0 - __bfloat162float(h0));
    __nv_bfloat16 l1 = __float2bfloat16(v1 - __bfloat162float(h1));
    hi = (u32)__bfloat16_as_ushort(h0) | ((u32)__bfloat16_as_ushort(h1) << 16);
    lo = (u32)__bfloat16_as_ushort(l0) | ((u32)__bfloat16_as_ushort(l1) << 16);
}

__device__ __forceinline__ void ldsm_x4(u32 addr, u32& r0, u32& r1, u32& r2, u32& r3) {
    asm volatile("ldmatrix.sync.aligned.m8n8.x4.shared.b16 {%0,%1,%2,%3}, [%4];"
                 : "=r"(r0), "=r"(r1), "=r"(r2), "=r"(r3) : "r"(addr));
}
__device__ __forceinline__ void ldsm_x2(u32 addr, u32& r0, u32& r1) {
    asm volatile("ldmatrix.sync.aligned.m8n8.x2.shared.b16 {%0,%1}, [%2];"
                 : "=r"(r0), "=r"(r1) : "r"(addr));
}
__device__ __forceinline__ void mma_bf16(float* c, u32 a0, u32 a1, u32 a2, u32 a3,
                                         u32 b0, u32 b1) {
    asm volatile("mma.sync.aligned.m16n8k16.row.col.f32.bf16.bf16.f32 "
                 "{%0,%1,%2,%3}, {%4,%5,%6,%7}, {%8,%9}, {%0,%1,%2,%3};"
                 : "+f"(c[0]), "+f"(c[1]), "+f"(c[2]), "+f"(c[3])
                 : "r"(a0), "r"(a1), "r"(a2), "r"(a3), "r"(b0), "r"(b1));
}

// ---- MMA GEMM: bufHw[64, D_] = bufIO[64, FIN] @ Wg[FIN, D_] (2-split bf16) ----
// bufIO stride FINS. Output fp32 stride D_+4 at CH base. K chunked by 64.
template<int FIN, int FINS, int D_, int NCH>
__device__ void mma_gemm(float* __restrict__ smem, const float* __restrict__ Wg,
                         int tid) {
    constexpr int HWS = D_ + 4;
    constexpr int NB = D_ / 16;              // n8-tiles per warp (8 or 4)
    float* bufIO = smem + OFF_BUF0;
    float* bufHw = smem + OFF_CH;
    char* ch = (char*)(smem + OFF_CH);
    u32 ahS = (u32)__cvta_generic_to_shared(ch + CHB_AH);
    u32 alS = ahS + 8192;
    u32 bhS = (u32)__cvta_generic_to_shared(ch + CHB_BH);
    u32 blS = bhS + 16384;

    const int wid = tid >> 5, lane = tid & 31;
    const int mt = wid & 3, nh = wid >> 2;   // m-tile, n-half

    // lane-fixed ldmatrix row bases
    const int am = mt * 16 + (lane & 15);
    const u32 aRow = (u32)(am * 128), aKey = (u32)((am & 7) << 4);
    const int aC = (lane >> 4) * 16;
    const int bn0 = nh * (NB * 8) + (lane & 7);
    const int bC = ((lane >> 3) & 1) * 16;

    float acc[NB][4];
    #pragma unroll
    for (int j = 0; j < NB; j++) { acc[j][0] = acc[j][1] = acc[j][2] = acc[j][3] = 0.f; }

    for (int ch_i = 0; ch_i < NCH; ch_i++) {
        const int k0 = ch_i * 64;
        // A convert: 64 rows x 32 words
        for (int i = tid; i < 64 * 32; i += NTHR) {
            int m = i >> 5, w = i & 31, k = k0 + 2 * w;
            float v0 = (k < FIN) ? bufIO[m * FINS + k] : 0.f;
            float v1 = (k + 1 < FIN) ? bufIO[m * FINS + k + 1] : 0.f;
            u32 hi, lo;
            split2(v0, v1, hi, lo);
            u32 off = (u32)(m * 128 + ((4 * w) ^ ((m & 7) << 4)));
            *(u32*)(ch + CHB_AH + off) = hi;
            *(u32*)(ch + CHB_AL + off) = lo;
        }
        // B convert (transpose): D_ n-rows x 32 words; LDG coalesced over n
        for (int i = tid; i < D_ * 32; i += NTHR) {
            int w = i / D_, n = i % D_, k = k0 + 2 * w;
            float v0 = (k < FIN) ? Wg[k * D_ + n] : 0.f;
            float v1 = (k + 1 < FIN) ? Wg[(k + 1) * D_ + n] : 0.f;
            u32 hi, lo;
            split2(v0, v1, hi, lo);
            u32 off = (u32)(n * 128 + ((4 * w) ^ ((n & 7) << 4)));
            *(u32*)(ch + CHB_BH + off) = hi;
            *(u32*)(ch + CHB_BL + off) = lo;
        }
        __syncthreads();
        #pragma unroll
        for (int ks = 0; ks < 4; ks++) {
            u32 aOff = aRow + (u32)((ks * 32 + aC) ^ (int)aKey);
            u32 ah0, ah1, ah2, ah3, al0, al1, al2, al3;
            ldsm_x4(ahS + aOff, ah0, ah1, ah2, ah3);
            ldsm_x4(alS + aOff, al0, al1, al2, al3);
            #pragma unroll
            for (int j = 0; j < NB; j++) {
                int bn = bn0 + j * 8;
                u32 bOff = (u32)(bn * 128 + ((ks * 32 + bC) ^ ((bn & 7) << 4)));
                u32 bh0, bh1, bl0, bl1;
                ldsm_x2(bhS + bOff, bh0, bh1);
                ldsm_x2(blS + bOff, bl0, bl1);
                mma_bf16(acc[j], ah0, ah1, ah2, ah3, bh0, bh1);
                mma_bf16(acc[j], ah0, ah1, ah2, ah3, bl0, bl1);
                mma_bf16(acc[j], al0, al1, al2, al3, bh0, bh1);
            }
        }
        __syncthreads();    // all ldmatrix done before next convert / epilogue alias
    }
    // epilogue: fragments -> bufHw (stride D_+4), aliases operand region
    {
        int r0 = mt * 16 + (lane >> 2);
        int c0 = (lane & 3) * 2;
        #pragma unroll
        for (int j = 0; j < NB; j++) {
            int col = nh * (NB * 8) + j * 8 + c0;
            *(float2*)(bufHw + r0 * HWS + col) = make_float2(acc[j][0], acc[j][1]);
            *(float2*)(bufHw + (r0 + 8) * HWS + col) = make_float2(acc[j][2], acc[j][3]);
        }
    }
    __syncthreads();
}

// ---- scalar GEMM for small layers (W resident fp32 in smem) ----
template<int FIN, int FINS, int F>
__device__ void scalar_gemm(float* __restrict__ smem, const float* __restrict__ Wsm,
                            int tid) {
    constexpr int D = 4 * F, HWS = D + 4;
    constexpr int RT = D / 16, NT_J = D / 4;
    float* bufIO = smem + OFF_BUF0;
    float* bufHw = smem + OFF_CH;
    const int jt = tid % NT_J, nt = tid / NT_J;
    const int j0 = jt * 4, n0 = nt * RT;
    float acc[RT][4];
    #pragma unroll
    for (int r = 0; r < RT; r++) { acc[r][0] = acc[r][1] = acc[r][2] = acc[r][3] = 0.f; }
    const float* hp = bufIO + n0 * FINS;
    #pragma unroll 4
    for (int k = 0; k < FIN; k += 4) {
        float4 a[RT];
        #pragma unroll
        for (int r = 0; r < RT; r++) a[r] = *(const float4*)(hp + r * FINS + k);
        #pragma unroll
        for (int kk = 0; kk < 4; kk++) {
            float4 w = *(const float4*)(Wsm + (k + kk) * D + j0);
            #pragma unroll
            for (int r = 0; r < RT; r++) {
                float av = kk == 0 ? a[r].x : kk == 1 ? a[r].y : kk == 2 ? a[r].z : a[r].w;
                acc[r][0] += av * w.x; acc[r][1] += av * w.y;
                acc[r][2] += av * w.z; acc[r][3] += av * w.w;
            }
        }
    }
    #pragma unroll
    for (int r = 0; r < RT; r++)
        *(float4*)(bufHw + (n0 + r) * HWS + j0) =
            make_float4(acc[r][0], acc[r][1], acc[r][2], acc[r][3]);
    __syncthreads();
}

// ---- attention: logits + per-target softmax aggregation (padded strides) ----
template<int F>
__device__ void attention(float* __restrict__ smem,
                          const float* __restrict__ a_s, const float* __restrict__ a_d,
                          const float* __restrict__ bias, bool apply_elu, int tid) {
    constexpr int D = 4 * F, HWS = D + 4, DS = D + 4, F4 = F / 4;
    float* bufIO = smem + OFF_BUF0;
    const float* hw = smem + OFF_CH;
    float* als = smem + OFF_ALS;
    float* ald = smem + OFF_ALD;
    float* smax = smem + OFF_SMAX;

    if (tid < NPG * 4) {
        int n = tid % NPG, h = tid / NPG;
        const float* hr = hw + n * HWS + h * F;
        float s1 = 0.0f, s2 = 0.0f;
        #pragma unroll
        for (int q = 0; q < F4; q++) {
            float4 v = *(const float4*)(hr + q * 4);
            float4 cs = *(const float4*)(a_s + h * F + q * 4);
            float4 cd = *(const float4*)(a_d + h * F + q * 4);
            s1 += v.x * cs.x + v.y * cs.y + v.z * cs.z + v.w * cs.w;
            s2 += v.x * cd.x + v.y * cd.y + v.z * cd.z + v.w * cd.w;
        }
        als[n * 5 + h] = s1;
        ald[n * 5 + h] = s2;
    }
    __syncthreads();
    if (tid < 128) {
        int h = tid >> 5, ln = tid & 31;
        float m2 = als[ln * 5 + h];
        if (ln + 32 < NPG) m2 = fmaxf(m2, als[(ln + 32) * 5 + h]);
        #pragma unroll
        for (int off = 16; off > 0; off >>= 1)
            m2 = fmaxf(m2, __shfl_xor_sync(0xffffffff, m2, off));
        if (ln == 0) smax[h] = m2;
    }
    __syncthreads();

    // segment_max == lrelu(max_s al_s + al_d) by monotonicity of leaky_relu.
    if (tid < NPG * 4) {
        int d = tid % NPG, h = tid / NPG;    // lanes share h -> hw reads broadcast
        float adv = ald[d * 5 + h];
        float sm = smax[h] + adv;
        float m = fmaxf(sm, 0.2f * sm);
        float den = 0.0f;
        float4 aacc[F4];
        #pragma unroll
        for (int q = 0; q < F4; q++) aacc[q] = make_float4(0.f, 0.f, 0.f, 0.f);
        const float* hwp = hw + h * F;
        #pragma unroll 2
        for (int s = 0; s < NPG; s++) {
            float xv = als[s * 5 + h] + adv;
            float e = fmaxf(xv, 0.2f * xv);
            float w = __expf(e - m);
            den += w;
            const float* hr = hwp + s * HWS;
            #pragma unroll
            for (int q = 0; q < F4; q++) {
                float4 v = *(const float4*)(hr + q * 4);
                aacc[q].x += w * v.x; aacc[q].y += w * v.y;
                aacc[q].z += w * v.z; aacc[q].w += w * v.w;
            }
        }
        float inv = 1.0f / den;
        float* orow = bufIO + d * DS + h * F;
        const float* bp = bias + h * F;
        #pragma unroll
        for (int q = 0; q < F4; q++) {
            float4 bv = *(const float4*)(bp + q * 4);
            float4 o;
            o.x = aacc[q].x * inv + bv.x; o.y = aacc[q].y * inv + bv.y;
            o.z = aacc[q].z * inv + bv.z; o.w = aacc[q].w * inv + bv.w;
            if (apply_elu) { o.x = elu_f(o.x); o.y = elu_f(o.y); o.z = elu_f(o.z); o.w = elu_f(o.w); }
            *(float4*)(orow + q * 4) = o;
        }
    }
    // zero padded rows 62..63 of the (re-striped) output
    for (int i = tid; i < 2 * DS; i += NTHR) bufIO[NPG * DS + i] = 0.0f;
    __syncthreads();
}

__global__ void __launch_bounds__(NTHR, 2)
eeg_gat_kernel(const float* __restrict__ x,
               const float* __restrict__ mcf_w, const float* __restrict__ mcf_b,
               const float* __restrict__ W0, const float* __restrict__ as0,
               const float* __restrict__ ad0, const float* __restrict__ b0,
               const float* __restrict__ W1, const float* __restrict__ as1,
               const float* __restrict__ ad1, const float* __restrict__ b1,
               const float* __restrict__ W2, const float* __restrict__ as2,
               const float* __restrict__ ad2, const float* __restrict__ b2,
               const float* __restrict__ W3, const float* __restrict__ as3,
               const float* __restrict__ ad3, const float* __restrict__ b3,
               const float* __restrict__ Wm1, const float* __restrict__ bm1,
               const float* __restrict__ Wm2, const float* __restrict__ bm2,
               const float* __restrict__ Wm3, const float* __restrict__ bm3,
               float* __restrict__ out) {
    extern __shared__ float smem[];
    const int tid = threadIdx.x;
    const int g = blockIdx.x;

    float* buf0 = smem + OFF_BUF0;

    // ---- EEG_MCf: stride-5 conv + ELU -> h0 [62, 160], row stride 164 ----
    float cw0 = mcf_w[0], cw1 = mcf_w[1], cw2 = mcf_w[2], cw3 = mcf_w[3], cw4 = mcf_w[4];
    float cb = mcf_b[0];
    for (int slot = tid; slot < NPG * 40; slot += NTHR) {
        int n = slot / 40, p = slot % 40;
        const float4* xp = (const float4*)(x + ((size_t)g * NPG + n) * LLEN + p * 20);
        float4 v0 = xp[0], v1 = xp[1], v2 = xp[2], v3 = xp[3], v4 = xp[4];
        float4 o;
        o.x = elu_f(v0.x * cw0 + v0.y * cw1 + v0.z * cw2 + v0.w * cw3 + v1.x * cw4 + cb);
        o.y = elu_f(v1.y * cw0 + v1.z * cw1 + v1.w * cw2 + v2.x * cw3 + v2.y * cw4 + cb);
        o.z = elu_f(v2.z * cw0 + v2.w * cw1 + v3.x * cw2 + v3.y * cw3 + v3.z * cw4 + cb);
        o.w = elu_f(v3.w * cw0 + v4.x * cw1 + v4.y * cw2 + v4.z * cw3 + v4.w * cw4 + cb);
        *(float4*)(buf0 + n * 164 + p * 4) = o;
    }
    for (int i = tid; i < 2 * 164; i += NTHR) buf0[NPG * 164 + i] = 0.0f;
    __syncthreads();

    // ---- L0/L1: tensor-core GEMM + scalar attention ----
    mma_gemm<160, 164, 128, 3>(smem, W0, tid);
    attention<32>(smem, as0, ad0, b0, true, tid);

    mma_gemm<128, 132, 64, 2>(smem, W1, tid);
    // stage W2/W3 fp32 (disjoint from bufHw L1 = 64*68*4 = 17408B < 34816)
    prefetch_w((float*)((char*)(smem + OFF_CH) + CHB_W2), W2, 64 * 32, tid);
    prefetch_w((float*)((char*)(smem + OFF_CH) + CHB_W3), W3, 32 * 16, tid);
    attention<16>(smem, as1, ad1, b1, true, tid);

    // ---- L2/L3: scalar GEMM + attention ----
    cp_wait_all();
    __syncthreads();
    scalar_gemm<64, 68, 8>(smem, (float*)((char*)(smem + OFF_CH) + CHB_W2), tid);
    attention<8>(smem, as2, ad2, b2, true, tid);
    scalar_gemm<32, 36, 4>(smem, (float*)((char*)(smem + OFF_CH) + CHB_W3), tid);
    attention<4>(smem, as3, ad3, b3, false, tid);
    // buf0 holds h3 [62, 16] at row stride 20 (rows 62..63 zero)

    // ---- embeddings output: tuple = (z, embeddings); z occupies [0, 1024) ----
    float* emb_out = out + NGRAPH * 4 + (size_t)g * (NPG * 16);
    for (int i = tid; i < NPG * 16; i += NTHR)
        emb_out[i] = buf0[(i / 16) * 20 + (i % 16)];

    // ---- global mean pool + MLP head ----
    float* gm = smem + OFF_GM;
    float* z1 = smem + OFF_Z1;
    float* z2 = smem + OFF_Z2;
    if (tid < 16) {
        float s = 0.0f;
        for (int d = 0; d < NPG; d++) s += buf0[d * 20 + tid];
        gm[tid] = s / 62.0f;
    }
    __syncthreads();
    if (tid < 16) {
        float s = bm1[tid];
        #pragma unroll
        for (int i = 0; i < 16; i++) s += gm[i] * Wm1[i * 16 + tid];
        z1[tid] = fmaxf(s, 0.0f);
    }
    __syncthreads();
    if (tid < 8) {
        float s = bm2[tid];
        #pragma unroll
        for (int i = 0; i < 16; i++) s += z1[i] * Wm2[i * 8 + tid];
        z2[tid] = fmaxf(s, 0.0f);
    }
    __syncthreads();
    if (tid < 4) {
        float s = bm3[tid];
        #pragma unroll
        for (int i = 0; i < 8; i++) s += z2[i] * Wm3[i * 4 + tid];
        out[g * 4 + tid] = s;
    }
}

extern "C" void kernel_launch(void* const* d_in, const int* in_sizes, int n_in,
                              void* d_out, int out_size) {
    const float* x     = (const float*)d_in[0];
    // d_in[1] = edge_index, d_in[2] = batch: fixed block-diagonal complete graph,
    // exploited analytically.
    const float* mcf_w = (const float*)d_in[3];
    const float* mcf_b = (const float*)d_in[4];
    const float* W0  = (const float*)d_in[5];
    const float* as0 = (const float*)d_in[6];
    const float* ad0 = (const float*)d_in[7];
    const float* b0  = (const float*)d_in[8];
    const float* W1  = (const float*)d_in[9];
    const float* as1 = (const float*)d_in[10];
    const float* ad1 = (const float*)d_in[11];
    const float* b1  = (const float*)d_in[12];
    const float* W2  = (const float*)d_in[13];
    const float* as2 = (const float*)d_in[14];
    const float* ad2 = (const float*)d_in[15];
    const float* b2  = (const float*)d_in[16];
    const float* W3  = (const float*)d_in[17];
    const float* as3 = (const float*)d_in[18];
    const float* ad3 = (const float*)d_in[19];
    const float* b3  = (const float*)d_in[20];
    const float* Wm1 = (const float*)d_in[21];
    const float* bm1 = (const float*)d_in[22];
    const float* Wm2 = (const float*)d_in[23];
    const float* bm2 = (const float*)d_in[24];
    const float* Wm3 = (const float*)d_in[25];
    const float* bm3 = (const float*)d_in[26];
    float* out = (float*)d_out;

    cudaFuncSetAttribute(eeg_gat_kernel,
                         cudaFuncAttributeMaxDynamicSharedMemorySize, SMEM_BYTES);
    eeg_gat_kernel<<<NGRAPH, NTHR, SMEM_BYTES>>>(
        x, mcf_w, mcf_b,
        W0, as0, ad0, b0, W1, as1, ad1, b1,
        W2, as2, ad2, b2, W3, as3, ad3, b3,
        Wm1, bm1, Wm2, bm2, Wm3, bm3, out);
}